// round 9
// baseline (speedup 1.0000x reference)
#include <cuda_runtime.h>
#include <cstdint>

// Embedding gather: out[row, :] = weight[idx[row], :]
// idx: 16384 int32, weight: 50257 x 1024 fp32, out: 16384 x 1024 fp32.
// One CTA per 8 rows (2048 CTAs). Rows are processed as 32-byte segments:
// 1024 segments/CTA, 256 threads x 4 segments. Weight reads use 256-bit
// ld.global.nc.L2::evict_last.v4.b64 (sm_103a requires 256-bit width for
// the evict_last hint) so the ~55 MiB unique-row read set pins in the
// 126 MB L2 across graph replays; stores stay streaming (.cs, evict-first)
// so DRAM carries only the compulsory write traffic in steady state.

static constexpr int ROW_BYTES    = 4096;
static constexpr int VOCAB        = 50257;
static constexpr int ROWS_PER_CTA = 8;
static constexpr int THREADS      = 256;
static constexpr int SEGS_PER_CTA = ROWS_PER_CTA * (ROW_BYTES / 32);  // 1024
static constexpr int SEGS_PER_THR = SEGS_PER_CTA / THREADS;           // 4

__device__ __forceinline__ ulonglong4 ldg_evl_256(const void* p) {
    ulonglong4 v;
    asm("ld.global.nc.L2::evict_last.v4.b64 {%0,%1,%2,%3}, [%4];"
        : "=l"(v.x), "=l"(v.y), "=l"(v.z), "=l"(v.w)
        : "l"(p));
    return v;
}

__device__ __forceinline__ void stg_cs_256(void* p, const ulonglong4& v) {
    // Two 128-bit streaming stores (evict-first).
    asm volatile("st.global.cs.v2.b64 [%0], {%1,%2};"
                 :: "l"(p), "l"(v.x), "l"(v.y) : "memory");
    asm volatile("st.global.cs.v2.b64 [%0], {%1,%2};"
                 :: "l"((char*)p + 16), "l"(v.z), "l"(v.w) : "memory");
}

__global__ __launch_bounds__(THREADS) void embedding_gather_kernel(
    const int* __restrict__ idx,
    const char* __restrict__ weight,
    char* __restrict__ out,
    int n_rows)
{
    const int t    = threadIdx.x;
    const int base = blockIdx.x * ROWS_PER_CTA;

    if (base + ROWS_PER_CTA <= n_rows) {
        // 8 indices as two vector loads (broadcast within CTA), clamped.
        const int4* ip = (const int4*)(idx + base);
        int4 i0 = __ldg(&ip[0]);
        int4 i1 = __ldg(&ip[1]);
        int r[ROWS_PER_CTA] = { i0.x, i0.y, i0.z, i0.w, i1.x, i1.y, i1.z, i1.w };
        #pragma unroll
        for (int i = 0; i < ROWS_PER_CTA; i++) {
            int v = r[i];
            r[i] = (v < 0) ? 0 : (v >= VOCAB ? VOCAB - 1 : v);
        }

        // 4 independent 256-bit loads, then 4 stores.
        ulonglong4 v[SEGS_PER_THR];
        #pragma unroll
        for (int j = 0; j < SEGS_PER_THR; j++) {
            int s    = t + j * THREADS;          // segment id 0..1023
            int row  = s >> 7;                   // s / 128
            int off  = (s & 127) << 5;           // (s % 128) * 32
            v[j] = ldg_evl_256(weight + (size_t)r[row] * ROW_BYTES + off);
        }
        #pragma unroll
        for (int j = 0; j < SEGS_PER_THR; j++) {
            int s   = t + j * THREADS;
            int row = s >> 7;
            int off = (s & 127) << 5;
            stg_cs_256(out + (size_t)(base + row) * ROW_BYTES + off, v[j]);
        }
    } else {
        // Tail (unused for 16384 rows, kept for safety). Plain path.
        const float4* wsrc = (const float4*)weight;
        float4* wdst = (float4*)out;
        for (int i = 0; i < ROWS_PER_CTA; i++) {
            int row = base + i;
            if (row >= n_rows) break;
            int v = __ldg(&idx[row]);
            v = (v < 0) ? 0 : (v >= VOCAB ? VOCAB - 1 : v);
            float4 w = __ldg(&wsrc[(size_t)v * 256 + t]);
            __stcs(&wdst[(size_t)row * 256 + t], w);
        }
    }
}

extern "C" void kernel_launch(void* const* d_in, const int* in_sizes, int n_in,
                              void* d_out, int out_size) {
    const int*  idx    = (const int*)d_in[0];     // (2048, 8) int32 on device
    const char* weight = (const char*)d_in[1];    // (50257, 1024) fp32
    char*       out    = (char*)d_out;            // (2048, 8, 1024) fp32

    int n_rows = in_sizes[0];                     // 16384
    int n_ctas = (n_rows + ROWS_PER_CTA - 1) / ROWS_PER_CTA;  // 2048
    embedding_gather_kernel<<<n_ctas, THREADS>>>(idx, weight, out, n_rows);
}

// round 10
// speedup vs baseline: 1.5028x; 1.5028x over previous
#include <cuda_runtime.h>
#include <cstdint>

// Embedding gather: out[row, :] = weight[idx[row], :]
// idx: 16384 int32, weight: 50257 x 1024 fp32, out: 16384 x 1024 fp32.
// One CTA per 8 rows (2048 CTAs); each thread owns one float4 column:
// 8 independent LDG.128 then 8 streaming STG.128.
//
// FINAL (R3/R7 config, measured best 16.86us twice). Steady-state moves
// 128 MiB per graph replay in 16.86us = 7.96 TB/s aggregate = ~99.5% of
// the 8 TB/s HBM3e spec. Falsified alternatives:
//   - TMA bulk-copy ring (R5): 25.3us — single-driver-thread serialization,
//     tma pipe 1.2%.
//   - launch_bounds(256,4) for MLP=8 (R4): 18.5us — MLP not binding.
//   - persistent grid (R6): 17.2us — wave quantization not a real cost.
//   - 256-bit loads + L2::evict_last pinning (R9): 25.3us — replays still
//     read the full set from DRAM; reg pressure killed load concurrency.

static constexpr int EMSIZE       = 1024;
static constexpr int VEC_PER_ROW  = EMSIZE / 4;   // 256 float4 per row
static constexpr int VOCAB        = 50257;
static constexpr int ROWS_PER_CTA = 8;

__global__ __launch_bounds__(256) void embedding_gather_kernel(
    const int* __restrict__ idx,
    const float4* __restrict__ weight,
    float4* __restrict__ out,
    int n_rows)
{
    const int t    = threadIdx.x;                       // column (0..255)
    const int base = blockIdx.x * ROWS_PER_CTA;

    if (base + ROWS_PER_CTA <= n_rows) {
        // 8 indices as two vector loads (broadcast within CTA).
        const int4* ip = (const int4*)(idx + base);
        int4 i0 = __ldg(&ip[0]);
        int4 i1 = __ldg(&ip[1]);
        int r[ROWS_PER_CTA] = { i0.x, i0.y, i0.z, i0.w, i1.x, i1.y, i1.z, i1.w };
        #pragma unroll
        for (int i = 0; i < ROWS_PER_CTA; i++) {
            int v = r[i];
            r[i] = (v < 0) ? 0 : (v >= VOCAB ? VOCAB - 1 : v);
        }
        float4 w[ROWS_PER_CTA];
        #pragma unroll
        for (int i = 0; i < ROWS_PER_CTA; i++)
            w[i] = __ldg(&weight[(size_t)r[i] * VEC_PER_ROW + t]);
        #pragma unroll
        for (int i = 0; i < ROWS_PER_CTA; i++)
            __stcs(&out[(size_t)(base + i) * VEC_PER_ROW + t], w[i]);
    } else {
        // Tail (unused for 16384 rows, kept for safety).
        for (int i = 0; i < ROWS_PER_CTA; i++) {
            int row = base + i;
            if (row >= n_rows) break;
            int v = __ldg(&idx[row]);
            v = (v < 0) ? 0 : (v >= VOCAB ? VOCAB - 1 : v);
            float4 w = __ldg(&weight[(size_t)v * VEC_PER_ROW + t]);
            __stcs(&out[(size_t)row * VEC_PER_ROW + t], w);
        }
    }
}

extern "C" void kernel_launch(void* const* d_in, const int* in_sizes, int n_in,
                              void* d_out, int out_size) {
    const int*    idx    = (const int*)d_in[0];     // (2048, 8) int32 on device
    const float4* weight = (const float4*)d_in[1];  // (50257, 1024) fp32
    float4*       out    = (float4*)d_out;          // (2048, 8, 1024) fp32

    int n_rows = in_sizes[0];                       // 16384
    int n_ctas = (n_rows + ROWS_PER_CTA - 1) / ROWS_PER_CTA;  // 2048
    embedding_gather_kernel<<<n_ctas, 256>>>(idx, weight, out, n_rows);
}